// round 2
// baseline (speedup 1.0000x reference)
#include <cuda_runtime.h>
#include <math.h>

// ---------------- problem constants ----------------
// B=16, C=256, H=W=64 -> N=4096, E=256, heads=8, R=64, d=32
#define BATCH 16
#define CIN   256
#define NTOK  4096
#define MR    1024          // r-projection rows (2*R*heads)
#define HEADS 8
#define HDIM  32
#define NREG  64

// ---------------- device scratch (no cudaMalloc allowed) ----------------
__device__ float g_r[(size_t)BATCH * MR * NTOK];                   // 268 MB: exp(r - max) after K2
__device__ float g_zinv[BATCH * NTOK];                             // 1/softmax denominator per token
__device__ float g_xp[(size_t)BATCH * HEADS * CIN * 128];          // pooled X: [bh][256][128]
__device__ float g_s[BATCH * HEADS * 128];                         // region column sums (normalized)
__device__ float g_pool[(size_t)BATCH * HEADS * 3 * HDIM * NREG];  // qr,kr,vr per (b,h)
__device__ float g_vals[(size_t)BATCH * HEADS * HDIM * NREG];      // post-attention region values
__device__ float g_W2[(size_t)BATCH * 256 * 512];                  // Wout folded into region values

// =====================================================================
// K1: r GEMM  R[b] = Wr (1024x256) @ X[b] (256x4096) + br
// 128x128x8 tile, 8x8 microtile, 256 threads
// =====================================================================
__global__ void __launch_bounds__(256) r_gemm(
    const float* __restrict__ x,
    const float* __restrict__ Wr, const float* __restrict__ br)
{
    const int b  = blockIdx.z;
    const int m0 = blockIdx.y * 128;
    const int n0 = blockIdx.x * 128;
    const float* X = x + (size_t)b * CIN * NTOK;
    float* C = g_r + (size_t)b * MR * NTOK;

    __shared__ float As[8][128];
    __shared__ float Bs[8][128];

    const int tid = threadIdx.x;
    const int tr = tid / 16, tc = tid % 16;
    const int am = tid >> 1, ak = (tid & 1) * 4;
    const float* Arow = Wr + (size_t)(m0 + am) * CIN;
    const int bk = tid >> 5, bn = (tid & 31) * 4;

    float acc[8][8];
    #pragma unroll
    for (int i = 0; i < 8; i++)
        #pragma unroll
        for (int j = 0; j < 8; j++) acc[i][j] = 0.f;

    for (int k0 = 0; k0 < CIN; k0 += 8) {
        float4 av = *(const float4*)(Arow + k0 + ak);
        As[ak + 0][am] = av.x; As[ak + 1][am] = av.y;
        As[ak + 2][am] = av.z; As[ak + 3][am] = av.w;
        float4 bv = *(const float4*)(X + (size_t)(k0 + bk) * NTOK + n0 + bn);
        *(float4*)&Bs[bk][bn] = bv;
        __syncthreads();
        #pragma unroll
        for (int kk = 0; kk < 8; kk++) {
            float ra[8], rb[8];
            #pragma unroll
            for (int i = 0; i < 8; i++) ra[i] = As[kk][tr * 8 + i];
            #pragma unroll
            for (int j = 0; j < 8; j++) rb[j] = Bs[kk][tc * 8 + j];
            #pragma unroll
            for (int i = 0; i < 8; i++)
                #pragma unroll
                for (int j = 0; j < 8; j++) acc[i][j] += ra[i] * rb[j];
        }
        __syncthreads();
    }

    #pragma unroll
    for (int i = 0; i < 8; i++) {
        const int m = m0 + tr * 8 + i;
        const float bias = br[m];
        #pragma unroll
        for (int j = 0; j < 8; j++)
            C[(size_t)m * NTOK + n0 + tc * 8 + j] = acc[i][j] + bias;
    }
}

// =====================================================================
// K2: softmax over the 1024 r-channels per token.
// Stores exp(v-max) in-place; 1/sum in g_zinv (normalization deferred).
// Block = 256 threads = 32 tokens x 8 channel-lanes.
// =====================================================================
__global__ void __launch_bounds__(256) softmax_r()
{
    const int b  = blockIdx.y;
    const int n0 = blockIdx.x * 32;
    const int tn = threadIdx.x & 31;
    const int tc = threadIdx.x >> 5;
    const int n  = n0 + tn;
    float* R = g_r + (size_t)b * MR * NTOK;

    __shared__ float red[8][33];
    __shared__ float red2[8][33];

    float m = -1e30f;
    for (int c = tc; c < MR; c += 8)
        m = fmaxf(m, R[(size_t)c * NTOK + n]);
    red[tc][tn] = m;
    __syncthreads();
    if (tc == 0) {
        float mm = red[0][tn];
        #pragma unroll
        for (int i = 1; i < 8; i++) mm = fmaxf(mm, red[i][tn]);
        red[0][tn] = mm;
    }
    __syncthreads();
    m = red[0][tn];

    float s = 0.f;
    for (int c = tc; c < MR; c += 8) {
        const size_t idx = (size_t)c * NTOK + n;
        const float e = expf(R[idx] - m);
        R[idx] = e;
        s += e;
    }
    red2[tc][tn] = s;
    __syncthreads();
    if (tc == 0) {
        float ss = 0.f;
        #pragma unroll
        for (int i = 0; i < 8; i++) ss += red2[i][tn];
        g_zinv[b * NTOK + n] = 1.0f / ss;
    }
}

// =====================================================================
// K3: pool X into regions: Xp[bh][c][j] = sum_n X[b][c][n] * Rn[h][j][n]
// where Rn = exp_r * zinv (normalized). Also S[bh][j] = sum_n Rn[j][n]
// (computed by the dchunk-0 block). grid = (128 bh, 4 dchunks of 64).
// =====================================================================
__global__ void __launch_bounds__(256) pool_x(const float* __restrict__ x)
{
    const int bh = blockIdx.x;
    const int b = bh >> 3, h = bh & 7;
    const int d0 = blockIdx.y * 64;
    const float* X = x + (size_t)b * CIN * NTOK + (size_t)d0 * NTOK;
    const float* Rbase = g_r + (size_t)b * MR * NTOK + (size_t)(h * 128) * NTOK;
    const float* zinv = g_zinv + b * NTOK;

    __shared__ float Xs[64][33];
    __shared__ float Rns[32][129];
    __shared__ float zs[32];

    const int tid = threadIdx.x;
    const int tr = tid >> 5, tc = tid & 31;

    float acc[8][4];
    #pragma unroll
    for (int i = 0; i < 8; i++)
        #pragma unroll
        for (int j = 0; j < 4; j++) acc[i][j] = 0.f;
    float sacc = 0.f;

    for (int n0 = 0; n0 < NTOK; n0 += 32) {
        if (tid < 32) zs[tid] = zinv[n0 + tid];
        __syncthreads();
        #pragma unroll
        for (int k = 0; k < 8; k++) {
            const int idx = tid + k * 256;
            Xs[idx >> 5][idx & 31] = X[(size_t)(idx >> 5) * NTOK + n0 + (idx & 31)];
        }
        #pragma unroll
        for (int k = 0; k < 16; k++) {
            const int idx = tid + k * 256;
            const int j = idx >> 5, t = idx & 31;
            Rns[t][j] = Rbase[(size_t)j * NTOK + n0 + t] * zs[t];
        }
        __syncthreads();
        #pragma unroll
        for (int t = 0; t < 32; t++) {
            float rv[4];
            #pragma unroll
            for (int jj = 0; jj < 4; jj++) rv[jj] = Rns[t][jj * 32 + tc];
            #pragma unroll
            for (int dd = 0; dd < 8; dd++) {
                const float xv = Xs[tr * 8 + dd][t];
                #pragma unroll
                for (int jj = 0; jj < 4; jj++) acc[dd][jj] += xv * rv[jj];
            }
        }
        if (blockIdx.y == 0 && tid < 128) {
            #pragma unroll
            for (int t = 0; t < 32; t++) sacc += Rns[t][tid];
        }
        __syncthreads();
    }

    float* Xp = g_xp + (size_t)bh * CIN * 128;
    #pragma unroll
    for (int dd = 0; dd < 8; dd++)
        #pragma unroll
        for (int jj = 0; jj < 4; jj++)
            Xp[(size_t)(d0 + tr * 8 + dd) * 128 + jj * 32 + tc] = acc[dd][jj];
    if (blockIdx.y == 0 && tid < 128)
        g_s[bh * 128 + tid] = sacc;
}

// =====================================================================
// K3.5: qr/kr/vr = per-head Wqkv slices @ Xp (+ bias * S).
// q uses Xp columns 0..63 (Rq), k/v use columns 64..127 (Rk).
// 192 threads: (mat, j) = (tid/64, tid%64); each computes a 32-d column.
// =====================================================================
__global__ void __launch_bounds__(192) qkvr_kernel(
    const float* __restrict__ Wqkv, const float* __restrict__ bqkv)
{
    const int bh = blockIdx.x;
    const int h = bh & 7;
    const int tid = threadIdx.x;
    const int mat = tid >> 6;          // 0=q, 1=k, 2=v
    const int j   = tid & 63;
    const int jj  = (mat == 0) ? j : j + 64;

    __shared__ float Ws[96][65];
    const float* Xp = g_xp + (size_t)bh * CIN * 128;

    float acc[32];
    #pragma unroll
    for (int d = 0; d < 32; d++) acc[d] = 0.f;

    for (int c0 = 0; c0 < CIN; c0 += 64) {
        for (int idx = tid; idx < 96 * 64; idx += 192)
            Ws[idx >> 6][idx & 63] = Wqkv[(size_t)(h * 96 + (idx >> 6)) * CIN + c0 + (idx & 63)];
        __syncthreads();
        #pragma unroll 8
        for (int cc = 0; cc < 64; cc++) {
            const float xv = Xp[(size_t)(c0 + cc) * 128 + jj];
            #pragma unroll
            for (int d = 0; d < 32; d++) acc[d] += Ws[mat * 32 + d][cc] * xv;
        }
        __syncthreads();
    }

    const float Sv = g_s[bh * 128 + jj];
    float* out = g_pool + (size_t)bh * 3 * HDIM * NREG + mat * 2048;
    #pragma unroll
    for (int d = 0; d < 32; d++)
        out[d * 64 + j] = acc[d] + bqkv[h * 96 + mat * 32 + d] * Sv;
}

// =====================================================================
// K4: tiny region attention per (b,h)
// =====================================================================
__global__ void __launch_bounds__(256) attn_kernel()
{
    const int bh = blockIdx.x;
    const float* pool = g_pool + (size_t)bh * 3 * HDIM * NREG;
    __shared__ float qr[2048], kr[2048], vr[2048];
    __shared__ float L[64][65];
    const int tid = threadIdx.x;

    for (int i = tid; i < 2048; i += 256) {
        qr[i] = pool[i]; kr[i] = pool[2048 + i]; vr[i] = pool[4096 + i];
    }
    __syncthreads();

    const float scale = rsqrtf(32.0f);
    for (int i = tid; i < 4096; i += 256) {
        const int q = i >> 6, k = i & 63;
        float s = 0.f;
        #pragma unroll
        for (int d = 0; d < 32; d++) s += qr[d * 64 + q] * kr[d * 64 + k];
        L[q][k] = s * scale;
    }
    __syncthreads();
    if (tid < 64) {
        const int q = tid;
        float m = -1e30f;
        #pragma unroll
        for (int k = 0; k < 64; k++) m = fmaxf(m, L[q][k]);
        float s = 0.f;
        #pragma unroll
        for (int k = 0; k < 64; k++) { const float e = expf(L[q][k] - m); L[q][k] = e; s += e; }
        const float inv = 1.f / s;
        #pragma unroll
        for (int k = 0; k < 64; k++) L[q][k] *= inv;
    }
    __syncthreads();
    float* out = g_vals + (size_t)bh * HDIM * NREG;
    for (int i = tid; i < 2048; i += 256) {
        const int d = i >> 6, q = i & 63;
        float s = 0.f;
        #pragma unroll
        for (int k = 0; k < 64; k++) s += vr[d * 64 + k] * L[q][k];
        out[i] = s;
    }
}

// =====================================================================
// K5: fold Wout into region values
// =====================================================================
__global__ void __launch_bounds__(256) w2_kernel(const float* __restrict__ Wout)
{
    const int b = blockIdx.y;
    const int i = blockIdx.x * 256 + threadIdx.x;
    const int c = i >> 9, hq = i & 511;
    const int h = hq >> 6, q = hq & 63;
    const float* vals = g_vals + (size_t)(b * 8 + h) * HDIM * NREG;
    float s = 0.f;
    #pragma unroll
    for (int d = 0; d < 32; d++)
        s += Wout[c * 256 + h * 32 + d] * vals[d * 64 + q];
    g_W2[((size_t)b * 256 + c) * 512 + hq] = s;
}

// =====================================================================
// K6: expand GEMM + residual epilogue
// =====================================================================
__global__ void __launch_bounds__(256) out_gemm(
    float* __restrict__ out, const float* __restrict__ x,
    const float* __restrict__ bout, const float* __restrict__ alpha)
{
    const int b  = blockIdx.z;
    const int m0 = blockIdx.y * 128;
    const int n0 = blockIdx.x * 128;
    const float* A = g_W2 + (size_t)b * 256 * 512;
    const float* Bbase = g_r + (size_t)b * MR * NTOK;

    __shared__ float As[8][128];
    __shared__ float Bs[8][128];

    const int tid = threadIdx.x;
    const int tr = tid / 16, tc = tid % 16;
    const int am = tid >> 1, ak = (tid & 1) * 4;
    const int bk = tid >> 5, bn = (tid & 31) * 4;

    float acc[8][8];
    #pragma unroll
    for (int i = 0; i < 8; i++)
        #pragma unroll
        for (int j = 0; j < 8; j++) acc[i][j] = 0.f;

    for (int k0 = 0; k0 < 512; k0 += 8) {
        float4 av = *(const float4*)(A + (size_t)(m0 + am) * 512 + k0 + ak);
        As[ak + 0][am] = av.x; As[ak + 1][am] = av.y;
        As[ak + 2][am] = av.z; As[ak + 3][am] = av.w;
        const int kk = k0 + bk;
        const int row = ((kk >> 6) << 7) + (kk & 63);       // (h,q) -> h*128+q
        float4 bv = *(const float4*)(Bbase + (size_t)row * NTOK + n0 + bn);
        *(float4*)&Bs[bk][bn] = bv;
        __syncthreads();
        #pragma unroll
        for (int kk2 = 0; kk2 < 8; kk2++) {
            float ra[8], rb[8];
            #pragma unroll
            for (int i = 0; i < 8; i++) ra[i] = As[kk2][tr * 8 + i];
            #pragma unroll
            for (int j = 0; j < 8; j++) rb[j] = Bs[kk2][tc * 8 + j];
            #pragma unroll
            for (int i = 0; i < 8; i++)
                #pragma unroll
                for (int j = 0; j < 8; j++) acc[i][j] += ra[i] * rb[j];
        }
        __syncthreads();
    }

    const float alphav = *alpha;
    #pragma unroll
    for (int i = 0; i < 8; i++) {
        const int c = m0 + tr * 8 + i;
        const float bo = bout[c];
        #pragma unroll
        for (int j = 0; j < 8; j++) {
            const int n = n0 + tc * 8 + j;
            const float zi = g_zinv[b * NTOK + n];
            const size_t idx = ((size_t)b * 256 + c) * (size_t)NTOK + n;
            out[idx] = x[idx] + alphav * (acc[i][j] * zi + bo);
        }
    }
}

// =====================================================================
extern "C" void kernel_launch(void* const* d_in, const int* in_sizes, int n_in,
                              void* d_out, int out_size)
{
    const float* x     = (const float*)d_in[0];
    const float* Wqkv  = (const float*)d_in[1];
    const float* bqkv  = (const float*)d_in[2];
    const float* Wr    = (const float*)d_in[3];
    const float* br    = (const float*)d_in[4];
    const float* Wout  = (const float*)d_in[5];
    const float* bout  = (const float*)d_in[6];
    const float* alpha = (const float*)d_in[7];
    float* out = (float*)d_out;

    dim3 g1(NTOK / 128, MR / 128, BATCH);
    r_gemm<<<g1, 256>>>(x, Wr, br);

    dim3 g2(NTOK / 32, BATCH);
    softmax_r<<<g2, 256>>>();

    dim3 g3(BATCH * HEADS, 4);
    pool_x<<<g3, 256>>>(x);

    qkvr_kernel<<<BATCH * HEADS, 192>>>(Wqkv, bqkv);

    attn_kernel<<<BATCH * HEADS, 256>>>();

    w2_kernel<<<dim3(512, BATCH), 256>>>(Wout);

    dim3 g6(NTOK / 128, 256 / 128, BATCH);
    out_gemm<<<g6, 256>>>(out, x, bout, alpha);
}

// round 5
// speedup vs baseline: 1.6517x; 1.6517x over previous
#include <cuda_runtime.h>
#include <cuda_bf16.h>
#include <math.h>
#include <stdint.h>

// ---------------- problem constants ----------------
#define BATCH 16
#define CIN   256
#define NTOK  4096
#define MR    1024
#define HEADS 8

// ---------------- device scratch ----------------
__device__ float g_r[(size_t)BATCH * MR * NTOK];     // raw r, then exp(r-max) in place
__device__ float g_zinv[BATCH * NTOK];               // 1/sum per token
__device__ float g_s[BATCH * MR];                    // normalized region column sums
__device__ float g_xp[(size_t)BATCH * HEADS * CIN * 128];
__device__ float g_pool[(size_t)BATCH * HEADS * 3 * 32 * 64];
__device__ float g_vals[(size_t)BATCH * HEADS * 32 * 64];
__device__ float g_W2[(size_t)BATCH * 256 * 512];

#define SWZ(bo) ((bo) ^ (((bo) >> 3) & 0x70))

// smem: four 128x64 bf16 tiles (128B rows, SW128-swizzled)
#define SM_AH 0
#define SM_AL 16384
#define SM_BH 32768
#define SM_BL 49152
#define SMEM_BYTES 65536

// ---------------- mma.sync (sm_80+; compiles for sm_100) ----------------
__device__ __forceinline__ void mma16816(float* c, const uint32_t* a, uint32_t b0, uint32_t b1) {
    asm volatile(
        "mma.sync.aligned.m16n8k16.row.col.f32.bf16.bf16.f32 "
        "{%0,%1,%2,%3}, {%4,%5,%6,%7}, {%8,%9}, {%0,%1,%2,%3};"
        : "+f"(c[0]), "+f"(c[1]), "+f"(c[2]), "+f"(c[3])
        : "r"(a[0]), "r"(a[1]), "r"(a[2]), "r"(a[3]), "r"(b0), "r"(b1));
}

// ---- tile loaders: f32 -> (hi,lo) bf16, SW128-swizzled [128 rows x 64 k] ----
// 256 threads. A slots.
__device__ __forceinline__ void load_direct_A(char* smem, const float* src, size_t rstride) {
    const int tid = threadIdx.x;
    #pragma unroll
    for (int it = 0; it < 16; it++) {
        const int i = tid + it * 256;
        const int row = i >> 5;
        const int kp = (i & 31) * 2;
        float2 v = *(const float2*)(src + (size_t)row * rstride + kp);
        __nv_bfloat16 h0 = __float2bfloat16(v.x);
        __nv_bfloat16 h1 = __float2bfloat16(v.y);
        __nv_bfloat16 l0 = __float2bfloat16(v.x - __bfloat162float(h0));
        __nv_bfloat16 l1 = __float2bfloat16(v.y - __bfloat162float(h1));
        const uint32_t sw = SWZ((uint32_t)(row * 128 + kp * 2));
        __nv_bfloat162 hp; hp.x = h0; hp.y = h1;
        __nv_bfloat162 lp; lp.x = l0; lp.y = l1;
        *(__nv_bfloat162*)(smem + SM_AH + sw) = hp;
        *(__nv_bfloat162*)(smem + SM_AL + sw) = lp;
    }
}

// B slots, row-major source [row][k], optional per-k scale z
__device__ __forceinline__ void load_direct_B(char* smem, const float* src, size_t rstride,
                                              const float* z) {
    const int tid = threadIdx.x;
    #pragma unroll
    for (int it = 0; it < 16; it++) {
        const int i = tid + it * 256;
        const int row = i >> 5;
        const int kp = (i & 31) * 2;
        float2 v = *(const float2*)(src + (size_t)row * rstride + kp);
        if (z) { v.x *= z[kp]; v.y *= z[kp + 1]; }
        __nv_bfloat16 h0 = __float2bfloat16(v.x);
        __nv_bfloat16 h1 = __float2bfloat16(v.y);
        __nv_bfloat16 l0 = __float2bfloat16(v.x - __bfloat162float(h0));
        __nv_bfloat16 l1 = __float2bfloat16(v.y - __bfloat162float(h1));
        const uint32_t sw = SWZ((uint32_t)(row * 128 + kp * 2));
        __nv_bfloat162 hp; hp.x = h0; hp.y = h1;
        __nv_bfloat162 lp; lp.x = l0; lp.y = l1;
        *(__nv_bfloat162*)(smem + SM_BH + sw) = hp;
        *(__nv_bfloat162*)(smem + SM_BL + sw) = lp;
    }
}

// transposed B loader: src S[k][n] (n contiguous) -> smem [n-row][k]
__device__ __forceinline__ void load_trans_B(char* smem, const float* src, size_t nstride) {
    const int tid = threadIdx.x;
    #pragma unroll
    for (int it = 0; it < 32; it++) {
        const int i = tid + it * 256;
        const int k = i >> 7;
        const int n = i & 127;
        const float v = src[(size_t)k * nstride + n];
        __nv_bfloat16 h = __float2bfloat16(v);
        __nv_bfloat16 l = __float2bfloat16(v - __bfloat162float(h));
        const uint32_t sw = SWZ((uint32_t)(n * 128 + k * 2));
        *(__nv_bfloat16*)(smem + SM_BH + sw) = h;
        *(__nv_bfloat16*)(smem + SM_BL + sw) = l;
    }
}

// ---- per-chunk compute: warp tile 32(m) x 64(n), K=64, bf16x3 split ----
__device__ __forceinline__ void compute_chunk(const char* smem, float acc[2][8][4],
                                              int wm, int wn, int g, int tig) {
    #pragma unroll
    for (int ks = 0; ks < 4; ks++) {
        const int kk = ks * 16;
        const int c0 = (kk + tig * 2) * 2;       // byte col
        const int c1 = (kk + 8 + tig * 2) * 2;
        uint32_t ah[2][4], al[2][4];
        #pragma unroll
        for (int mt = 0; mt < 2; mt++) {
            const int r0 = (wm + mt * 16 + g) * 128;
            const int r1 = r0 + 8 * 128;
            ah[mt][0] = *(const uint32_t*)(smem + SM_AH + SWZ(r0 + c0));
            ah[mt][1] = *(const uint32_t*)(smem + SM_AH + SWZ(r1 + c0));
            ah[mt][2] = *(const uint32_t*)(smem + SM_AH + SWZ(r0 + c1));
            ah[mt][3] = *(const uint32_t*)(smem + SM_AH + SWZ(r1 + c1));
            al[mt][0] = *(const uint32_t*)(smem + SM_AL + SWZ(r0 + c0));
            al[mt][1] = *(const uint32_t*)(smem + SM_AL + SWZ(r1 + c0));
            al[mt][2] = *(const uint32_t*)(smem + SM_AL + SWZ(r0 + c1));
            al[mt][3] = *(const uint32_t*)(smem + SM_AL + SWZ(r1 + c1));
        }
        #pragma unroll
        for (int nt = 0; nt < 8; nt++) {
            const int nr = (wn + nt * 8 + g) * 128;
            const uint32_t bh0 = *(const uint32_t*)(smem + SM_BH + SWZ(nr + c0));
            const uint32_t bh1 = *(const uint32_t*)(smem + SM_BH + SWZ(nr + c1));
            const uint32_t bl0 = *(const uint32_t*)(smem + SM_BL + SWZ(nr + c0));
            const uint32_t bl1 = *(const uint32_t*)(smem + SM_BL + SWZ(nr + c1));
            #pragma unroll
            for (int mt = 0; mt < 2; mt++) {
                mma16816(acc[mt][nt], ah[mt], bh0, bh1);
                mma16816(acc[mt][nt], al[mt], bh0, bh1);
                mma16816(acc[mt][nt], ah[mt], bl0, bl1);
            }
        }
    }
}

// =====================================================================
// K0: zero region sums
// =====================================================================
__global__ void zero_s() { g_s[blockIdx.x * 1024 + threadIdx.x] = 0.f; }

// =====================================================================
// K1: r GEMM: g_r[b] = Wr(1024x256) @ X[b](256x4096) + br
// =====================================================================
__global__ void __launch_bounds__(256) tc_r_gemm(
    const float* __restrict__ x,
    const float* __restrict__ Wr, const float* __restrict__ br)
{
    extern __shared__ char smem[];
    const int tid = threadIdx.x;
    const int b = blockIdx.z, m0 = blockIdx.y * 128, n0 = blockIdx.x * 128;
    const float* X = x + (size_t)b * CIN * NTOK;

    const int lane = tid & 31, wid = tid >> 5;
    const int wm = (wid >> 1) * 32, wn = (wid & 1) * 64;
    const int g = lane >> 2, tig = lane & 3;

    float acc[2][8][4];
    #pragma unroll
    for (int i = 0; i < 2; i++)
        #pragma unroll
        for (int j = 0; j < 8; j++)
            #pragma unroll
            for (int k = 0; k < 4; k++) acc[i][j][k] = 0.f;

    for (int k0 = 0; k0 < CIN; k0 += 64) {
        load_direct_A(smem, Wr + (size_t)m0 * CIN + k0, CIN);
        load_trans_B(smem, X + (size_t)k0 * NTOK + n0, NTOK);
        __syncthreads();
        compute_chunk(smem, acc, wm, wn, g, tig);
        __syncthreads();
    }

    #pragma unroll
    for (int mt = 0; mt < 2; mt++) {
        const int m_a = m0 + wm + mt * 16 + g;
        const int m_b = m_a + 8;
        const float ba = br[m_a], bb = br[m_b];
        float* Ca = g_r + (size_t)b * MR * NTOK + (size_t)m_a * NTOK + n0 + wn;
        float* Cb = g_r + (size_t)b * MR * NTOK + (size_t)m_b * NTOK + n0 + wn;
        #pragma unroll
        for (int nt = 0; nt < 8; nt++) {
            const int nn = nt * 8 + tig * 2;
            float2 va; va.x = acc[mt][nt][0] + ba; va.y = acc[mt][nt][1] + ba;
            float2 vb; vb.x = acc[mt][nt][2] + bb; vb.y = acc[mt][nt][3] + bb;
            *(float2*)(Ca + nn) = va;
            *(float2*)(Cb + nn) = vb;
        }
    }
}

// =====================================================================
// K2: channel softmax; stores exp(v - max) in place, zinv per token,
// and accumulates normalized row sums S (L2-hot re-read).
// =====================================================================
__global__ void __launch_bounds__(256) softmax_r()
{
    const int b  = blockIdx.y;
    const int n0 = blockIdx.x * 32;
    const int tn = threadIdx.x & 31;
    const int tc = threadIdx.x >> 5;
    const int n  = n0 + tn;
    float* R = g_r + (size_t)b * MR * NTOK;

    __shared__ float red[8][33];
    __shared__ float red2[8][33];
    __shared__ float zs[32];

    float m = -1e30f;
    for (int c = tc; c < MR; c += 8)
        m = fmaxf(m, R[(size_t)c * NTOK + n]);
    red[tc][tn] = m;
    __syncthreads();
    if (tc == 0) {
        float mm = red[0][tn];
        #pragma unroll
        for (int i = 1; i < 8; i++) mm = fmaxf(mm, red[i][tn]);
        red[0][tn] = mm;
    }
    __syncthreads();
    m = red[0][tn];

    float s = 0.f;
    for (int c = tc; c < MR; c += 8) {
        const size_t idx = (size_t)c * NTOK + n;
        const float e = expf(R[idx] - m);
        R[idx] = e;
        s += e;
    }
    red2[tc][tn] = s;
    __syncthreads();
    if (tc == 0) {
        float ss = 0.f;
        #pragma unroll
        for (int i = 0; i < 8; i++) ss += red2[i][tn];
        const float zi = 1.0f / ss;
        g_zinv[b * NTOK + n] = zi;
        zs[tn] = zi;
    }
    __syncthreads();

    for (int row = threadIdx.x; row < MR; row += 256) {
        const float* Rr = R + (size_t)row * NTOK + n0;
        float acc = 0.f;
        #pragma unroll 8
        for (int t = 0; t < 32; t++) acc += Rr[t] * zs[t];
        atomicAdd(&g_s[b * MR + row], acc);
    }
}

// =====================================================================
// K3: pooling: Xp[bh] = X[b](256x4096) @ Rn[bh]^T(4096x128), zinv folded in
// grid (128 bh, 2 m-tiles)
// =====================================================================
__global__ void __launch_bounds__(256) tc_pool(const float* __restrict__ x)
{
    extern __shared__ char smem[];
    const int tid = threadIdx.x;
    const int bh = blockIdx.x, b = bh >> 3, h = bh & 7;
    const int m0 = blockIdx.y * 128;
    const float* X = x + (size_t)b * CIN * NTOK + (size_t)m0 * NTOK;
    const float* Rb = g_r + (size_t)b * MR * NTOK + (size_t)(h * 128) * NTOK;
    const float* z = g_zinv + b * NTOK;

    const int lane = tid & 31, wid = tid >> 5;
    const int wm = (wid >> 1) * 32, wn = (wid & 1) * 64;
    const int g = lane >> 2, tig = lane & 3;

    float acc[2][8][4];
    #pragma unroll
    for (int i = 0; i < 2; i++)
        #pragma unroll
        for (int j = 0; j < 8; j++)
            #pragma unroll
            for (int k = 0; k < 4; k++) acc[i][j][k] = 0.f;

    for (int k0 = 0; k0 < NTOK; k0 += 64) {
        load_direct_A(smem, X + k0, NTOK);
        load_direct_B(smem, Rb + k0, NTOK, z + k0);
        __syncthreads();
        compute_chunk(smem, acc, wm, wn, g, tig);
        __syncthreads();
    }

    float* Xp = g_xp + (size_t)bh * CIN * 128;
    #pragma unroll
    for (int mt = 0; mt < 2; mt++) {
        const int r_a = m0 + wm + mt * 16 + g;
        const int r_b = r_a + 8;
        #pragma unroll
        for (int nt = 0; nt < 8; nt++) {
            const int nn = wn + nt * 8 + tig * 2;
            float2 va; va.x = acc[mt][nt][0]; va.y = acc[mt][nt][1];
            float2 vb; vb.x = acc[mt][nt][2]; vb.y = acc[mt][nt][3];
            *(float2*)(Xp + (size_t)r_a * 128 + nn) = va;
            *(float2*)(Xp + (size_t)r_b * 128 + nn) = vb;
        }
    }
}

// =====================================================================
// K3.5: qr/kr/vr from pooled X. grid (128 bh, 2 jsub), 256 threads
// =====================================================================
__global__ void __launch_bounds__(256) qkvr_kernel(
    const float* __restrict__ Wqkv, const float* __restrict__ bqkv)
{
    const int bh = blockIdx.x;
    const int b = bh >> 3, h = bh & 7;
    const int jsub = blockIdx.y;
    const int tid = threadIdx.x;
    const int jloc = tid & 31;
    const int j = jsub * 32 + jloc;
    const int g = tid >> 5;

    __shared__ float Ws[96][33];
    __shared__ float Xs[32][129];
    const float* Xp = g_xp + (size_t)bh * CIN * 128;

    float acc[12];
    #pragma unroll
    for (int i = 0; i < 12; i++) acc[i] = 0.f;

    for (int c0 = 0; c0 < CIN; c0 += 32) {
        for (int idx = tid; idx < 96 * 32; idx += 256)
            Ws[idx >> 5][idx & 31] = Wqkv[(size_t)(h * 96 + (idx >> 5)) * CIN + c0 + (idx & 31)];
        for (int idx = tid; idx < 32 * 128; idx += 256)
            Xs[idx >> 7][idx & 127] = Xp[(size_t)(c0 + (idx >> 7)) * 128 + (idx & 127)];
        __syncthreads();
        #pragma unroll 8
        for (int cc = 0; cc < 32; cc++) {
            const float xq = Xs[cc][j];
            const float xk = Xs[cc][j + 64];
            #pragma unroll
            for (int i = 0; i < 12; i++) {
                const int row = g * 12 + i;
                acc[i] += Ws[row][cc] * (row < 32 ? xq : xk);
            }
        }
        __syncthreads();
    }

    float* out = g_pool + (size_t)bh * 3 * 2048;
    #pragma unroll
    for (int i = 0; i < 12; i++) {
        const int row = g * 12 + i;
        const int mat = row >> 5, d = row & 31;
        const int jj = (mat == 0) ? j : j + 64;
        const float Sv = g_s[b * MR + h * 128 + jj];
        out[mat * 2048 + d * 64 + j] = acc[i] + bqkv[h * 96 + row] * Sv;
    }
}

// =====================================================================
// K4: tiny region attention per (b,h)
// =====================================================================
__global__ void __launch_bounds__(256) attn_kernel()
{
    const int bh = blockIdx.x;
    const float* pool = g_pool + (size_t)bh * 3 * 2048;
    __shared__ float qr[2048], kr[2048], vr[2048];
    __shared__ float L[64][65];
    const int tid = threadIdx.x;

    for (int i = tid; i < 2048; i += 256) {
        qr[i] = pool[i]; kr[i] = pool[2048 + i]; vr[i] = pool[4096 + i];
    }
    __syncthreads();

    const float scale = rsqrtf(32.0f);
    for (int i = tid; i < 4096; i += 256) {
        const int q = i >> 6, k = i & 63;
        float s = 0.f;
        #pragma unroll
        for (int d = 0; d < 32; d++) s += qr[d * 64 + q] * kr[d * 64 + k];
        L[q][k] = s * scale;
    }
    __syncthreads();
    if (tid < 64) {
        const int q = tid;
        float m = -1e30f;
        #pragma unroll
        for (int k = 0; k < 64; k++) m = fmaxf(m, L[q][k]);
        float s = 0.f;
        #pragma unroll
        for (int k = 0; k < 64; k++) { const float e = expf(L[q][k] - m); L[q][k] = e; s += e; }
        const float inv = 1.f / s;
        #pragma unroll
        for (int k = 0; k < 64; k++) L[q][k] *= inv;
    }
    __syncthreads();
    float* out = g_vals + (size_t)bh * 2048;
    for (int i = tid; i < 2048; i += 256) {
        const int d = i >> 6, q = i & 63;
        float s = 0.f;
        #pragma unroll
        for (int k = 0; k < 64; k++) s += vr[d * 64 + k] * L[q][k];
        out[i] = s;
    }
}

// =====================================================================
// K5: fold Wout into region values
// =====================================================================
__global__ void __launch_bounds__(256) w2_kernel(const float* __restrict__ Wout)
{
    const int b = blockIdx.y;
    const int i = blockIdx.x * 256 + threadIdx.x;
    const int c = i >> 9, hq = i & 511;
    const int h = hq >> 6, q = hq & 63;
    const float* vals = g_vals + (size_t)(b * 8 + h) * 2048;
    float s = 0.f;
    #pragma unroll
    for (int d = 0; d < 32; d++)
        s += Wout[c * 256 + h * 32 + d] * vals[d * 64 + q];
    g_W2[((size_t)b * 256 + c) * 512 + hq] = s;
}

// =====================================================================
// K6: expand GEMM + residual epilogue
// C[b] = W2(256x512) @ Rsel(512x4096); out = x + alpha*(C*zinv + bout)
// =====================================================================
__global__ void __launch_bounds__(256) tc_out(
    float* __restrict__ out, const float* __restrict__ x,
    const float* __restrict__ bout, const float* __restrict__ alpha)
{
    extern __shared__ char smem[];
    const int tid = threadIdx.x;
    const int b = blockIdx.z, m0 = blockIdx.y * 128, n0 = blockIdx.x * 128;
    const float* A = g_W2 + (size_t)b * 256 * 512;
    const float* Rbase = g_r + (size_t)b * MR * NTOK;

    const int lane = tid & 31, wid = tid >> 5;
    const int wm = (wid >> 1) * 32, wn = (wid & 1) * 64;
    const int g = lane >> 2, tig = lane & 3;

    float acc[2][8][4];
    #pragma unroll
    for (int i = 0; i < 2; i++)
        #pragma unroll
        for (int j = 0; j < 8; j++)
            #pragma unroll
            for (int k = 0; k < 4; k++) acc[i][j][k] = 0.f;

    for (int k0 = 0; k0 < 512; k0 += 64) {
        load_direct_A(smem, A + (size_t)m0 * 512 + k0, 512);
        // chunk k0 covers r rows (k0>>6)*128 .. +63 (the Rq half of each head)
        load_trans_B(smem, Rbase + (size_t)((k0 >> 6) * 128) * NTOK + n0, NTOK);
        __syncthreads();
        compute_chunk(smem, acc, wm, wn, g, tig);
        __syncthreads();
    }

    const float av = *alpha;
    #pragma unroll
    for (int mt = 0; mt < 2; mt++) {
        const int c_a = m0 + wm + mt * 16 + g;
        const int c_b = c_a + 8;
        const float ba = bout[c_a], bb = bout[c_b];
        const size_t base_a = ((size_t)b * 256 + c_a) * NTOK + n0 + wn;
        const size_t base_b = ((size_t)b * 256 + c_b) * NTOK + n0 + wn;
        #pragma unroll
        for (int nt = 0; nt < 8; nt++) {
            const int nn = nt * 8 + tig * 2;
            const int n = n0 + wn + nn;
            const float z0 = g_zinv[b * NTOK + n];
            const float z1 = g_zinv[b * NTOK + n + 1];
            float2 xa = *(const float2*)(x + base_a + nn);
            float2 xb = *(const float2*)(x + base_b + nn);
            float2 oa, ob;
            oa.x = xa.x + av * (acc[mt][nt][0] * z0 + ba);
            oa.y = xa.y + av * (acc[mt][nt][1] * z1 + ba);
            ob.x = xb.x + av * (acc[mt][nt][2] * z0 + bb);
            ob.y = xb.y + av * (acc[mt][nt][3] * z1 + bb);
            *(float2*)(out + base_a + nn) = oa;
            *(float2*)(out + base_b + nn) = ob;
        }
    }
}

// =====================================================================
extern "C" void kernel_launch(void* const* d_in, const int* in_sizes, int n_in,
                              void* d_out, int out_size)
{
    const float* x     = (const float*)d_in[0];
    const float* Wqkv  = (const float*)d_in[1];
    const float* bqkv  = (const float*)d_in[2];
    const float* Wr    = (const float*)d_in[3];
    const float* br    = (const float*)d_in[4];
    const float* Wout  = (const float*)d_in[5];
    const float* bout  = (const float*)d_in[6];
    const float* alpha = (const float*)d_in[7];
    float* out = (float*)d_out;

    cudaFuncSetAttribute(tc_r_gemm, cudaFuncAttributeMaxDynamicSharedMemorySize, SMEM_BYTES);
    cudaFuncSetAttribute(tc_pool,   cudaFuncAttributeMaxDynamicSharedMemorySize, SMEM_BYTES);
    cudaFuncSetAttribute(tc_out,    cudaFuncAttributeMaxDynamicSharedMemorySize, SMEM_BYTES);

    zero_s<<<16, 1024>>>();

    dim3 g1(NTOK / 128, MR / 128, BATCH);
    tc_r_gemm<<<g1, 256, SMEM_BYTES>>>(x, Wr, br);

    dim3 g2(NTOK / 32, BATCH);
    softmax_r<<<g2, 256>>>();

    dim3 g3(BATCH * HEADS, 2);
    tc_pool<<<g3, 256, SMEM_BYTES>>>(x);

    dim3 g35(BATCH * HEADS, 2);
    qkvr_kernel<<<g35, 256>>>(Wqkv, bqkv);

    attn_kernel<<<BATCH * HEADS, 256>>>();

    w2_kernel<<<dim3(512, BATCH), 256>>>(Wout);

    dim3 g6(NTOK / 128, 256 / 128, BATCH);
    tc_out<<<g6, 256, SMEM_BYTES>>>(out, x, bout, alpha);
}

// round 6
// speedup vs baseline: 2.7228x; 1.6485x over previous
#include <cuda_runtime.h>
#include <cuda_fp16.h>
#include <math.h>
#include <stdint.h>

// ---------------- problem constants ----------------
#define BATCH 16
#define CIN   256
#define NTOK  4096
#define MR    1024
#define HEADS 8

// ---------------- device scratch ----------------
__device__ __half g_r[(size_t)BATCH * MR * NTOK];    // logits (fp16), then exp(v-max) in place
__device__ float g_zinv[BATCH * NTOK];               // 1/sum per token
__device__ float g_s[BATCH * MR];                    // normalized region column sums
__device__ float g_xp[(size_t)BATCH * HEADS * CIN * 128];
__device__ float g_pool[(size_t)BATCH * HEADS * 3 * 32 * 64];
__device__ float g_vals[(size_t)BATCH * HEADS * 32 * 64];
__device__ float g_W2[(size_t)BATCH * 256 * 512];

#define SWZ(bo) ((bo) ^ (((bo) >> 3) & 0x70))

// smem: two 128x64 fp16 tiles (128B rows, SW128-swizzled)
#define SM_A 0
#define SM_B 16384
#define SMEM_BYTES 32768

// ---------------- fp16 mma.sync (sm_80+) ----------------
__device__ __forceinline__ void mma16816(float* c, const uint32_t* a, uint32_t b0, uint32_t b1) {
    asm volatile(
        "mma.sync.aligned.m16n8k16.row.col.f32.f16.f16.f32 "
        "{%0,%1,%2,%3}, {%4,%5,%6,%7}, {%8,%9}, {%0,%1,%2,%3};"
        : "+f"(c[0]), "+f"(c[1]), "+f"(c[2]), "+f"(c[3])
        : "r"(a[0]), "r"(a[1]), "r"(a[2]), "r"(a[3]), "r"(b0), "r"(b1));
}

// ---- tile loaders -> fp16, SW128-swizzled [128 rows x 64 k] ----
// A slot, fp32 row-major source
__device__ __forceinline__ void load_A_f32(char* smem, const float* src, size_t rstride) {
    const int tid = threadIdx.x;
    #pragma unroll
    for (int it = 0; it < 16; it++) {
        const int i = tid + it * 256;
        const int row = i >> 5;
        const int kp = (i & 31) * 2;
        float2 v = *(const float2*)(src + (size_t)row * rstride + kp);
        __half2 h; h.x = __float2half(v.x); h.y = __float2half(v.y);
        *(__half2*)(smem + SM_A + SWZ((uint32_t)(row * 128 + kp * 2))) = h;
    }
}

// B slot, fp16 row-major source with per-k fp32 scale (pool: exp * zinv)
__device__ __forceinline__ void load_B_h16_scaled(char* smem, const __half* src, size_t rstride,
                                                  const float* z) {
    const int tid = threadIdx.x;
    #pragma unroll
    for (int it = 0; it < 16; it++) {
        const int i = tid + it * 256;
        const int row = i >> 5;
        const int kp = (i & 31) * 2;
        __half2 v = *(const __half2*)(src + (size_t)row * rstride + kp);
        __half2 h;
        h.x = __float2half(__half2float(v.x) * z[kp]);
        h.y = __float2half(__half2float(v.y) * z[kp + 1]);
        *(__half2*)(smem + SM_B + SWZ((uint32_t)(row * 128 + kp * 2))) = h;
    }
}

// B slot transposed, fp32 source S[k][n] (n contiguous) -> smem [n-row][k]
__device__ __forceinline__ void load_B_trans_f32(char* smem, const float* src, size_t nstride) {
    const int tid = threadIdx.x;
    #pragma unroll
    for (int it = 0; it < 32; it++) {
        const int i = tid + it * 256;
        const int k = i >> 7;
        const int n = i & 127;
        const float v = src[(size_t)k * nstride + n];
        *(__half*)(smem + SM_B + SWZ((uint32_t)(n * 128 + k * 2))) = __float2half(v);
    }
}

// B slot transposed, fp16 source S[k][n] -> smem [n-row][k]
__device__ __forceinline__ void load_B_trans_h16(char* smem, const __half* src, size_t nstride) {
    const int tid = threadIdx.x;
    #pragma unroll
    for (int it = 0; it < 16; it++) {
        const int p = tid + it * 256;
        const int k = p >> 6;
        const int np = (p & 63) * 2;
        __half2 v = *(const __half2*)(src + (size_t)k * nstride + np);
        *(__half*)(smem + SM_B + SWZ((uint32_t)(np * 128 + k * 2))) = v.x;
        *(__half*)(smem + SM_B + SWZ((uint32_t)((np + 1) * 128 + k * 2))) = v.y;
    }
}

// ---- per-chunk compute: warp tile 32(m) x 64(n), K=64, single fp16 term ----
__device__ __forceinline__ void compute_chunk(const char* smem, float acc[2][8][4],
                                              int wm, int wn, int g, int tig) {
    #pragma unroll
    for (int ks = 0; ks < 4; ks++) {
        const int kk = ks * 16;
        const int c0 = (kk + tig * 2) * 2;
        const int c1 = (kk + 8 + tig * 2) * 2;
        uint32_t a[2][4];
        #pragma unroll
        for (int mt = 0; mt < 2; mt++) {
            const int r0 = (wm + mt * 16 + g) * 128;
            const int r1 = r0 + 8 * 128;
            a[mt][0] = *(const uint32_t*)(smem + SM_A + SWZ(r0 + c0));
            a[mt][1] = *(const uint32_t*)(smem + SM_A + SWZ(r1 + c0));
            a[mt][2] = *(const uint32_t*)(smem + SM_A + SWZ(r0 + c1));
            a[mt][3] = *(const uint32_t*)(smem + SM_A + SWZ(r1 + c1));
        }
        #pragma unroll
        for (int nt = 0; nt < 8; nt++) {
            const int nr = (wn + nt * 8 + g) * 128;
            const uint32_t b0 = *(const uint32_t*)(smem + SM_B + SWZ(nr + c0));
            const uint32_t b1 = *(const uint32_t*)(smem + SM_B + SWZ(nr + c1));
            mma16816(acc[0][nt], a[0], b0, b1);
            mma16816(acc[1][nt], a[1], b0, b1);
        }
    }
}

// =====================================================================
// K0: zero region sums
// =====================================================================
__global__ void zero_s() { g_s[blockIdx.x * 1024 + threadIdx.x] = 0.f; }

// =====================================================================
// K1: r GEMM: g_r[b] = Wr(1024x256) @ X[b](256x4096) + br   (fp16 out)
// =====================================================================
__global__ void __launch_bounds__(256, 2) tc_r_gemm(
    const float* __restrict__ x,
    const float* __restrict__ Wr, const float* __restrict__ br)
{
    extern __shared__ char smem[];
    const int tid = threadIdx.x;
    const int b = blockIdx.z, m0 = blockIdx.y * 128, n0 = blockIdx.x * 128;
    const float* X = x + (size_t)b * CIN * NTOK;

    const int lane = tid & 31, wid = tid >> 5;
    const int wm = (wid >> 1) * 32, wn = (wid & 1) * 64;
    const int g = lane >> 2, tig = lane & 3;

    float acc[2][8][4];
    #pragma unroll
    for (int i = 0; i < 2; i++)
        #pragma unroll
        for (int j = 0; j < 8; j++)
            #pragma unroll
            for (int k = 0; k < 4; k++) acc[i][j][k] = 0.f;

    for (int k0 = 0; k0 < CIN; k0 += 64) {
        load_A_f32(smem, Wr + (size_t)m0 * CIN + k0, CIN);
        load_B_trans_f32(smem, X + (size_t)k0 * NTOK + n0, NTOK);
        __syncthreads();
        compute_chunk(smem, acc, wm, wn, g, tig);
        __syncthreads();
    }

    #pragma unroll
    for (int mt = 0; mt < 2; mt++) {
        const int m_a = m0 + wm + mt * 16 + g;
        const int m_b = m_a + 8;
        const float ba = br[m_a], bb = br[m_b];
        __half* Ca = g_r + (size_t)b * MR * NTOK + (size_t)m_a * NTOK + n0 + wn;
        __half* Cb = g_r + (size_t)b * MR * NTOK + (size_t)m_b * NTOK + n0 + wn;
        #pragma unroll
        for (int nt = 0; nt < 8; nt++) {
            const int nn = nt * 8 + tig * 2;
            __half2 va; va.x = __float2half(acc[mt][nt][0] + ba); va.y = __float2half(acc[mt][nt][1] + ba);
            __half2 vb; vb.x = __float2half(acc[mt][nt][2] + bb); vb.y = __float2half(acc[mt][nt][3] + bb);
            *(__half2*)(Ca + nn) = va;
            *(__half2*)(Cb + nn) = vb;
        }
    }
}

// =====================================================================
// K2: channel softmax on fp16 logits; stores exp(v-max) fp16 in place,
// zinv fp32, and accumulates normalized row sums S.
// =====================================================================
__global__ void __launch_bounds__(256) softmax_r()
{
    const int b  = blockIdx.y;
    const int n0 = blockIdx.x * 32;
    const int tn = threadIdx.x & 31;
    const int tc = threadIdx.x >> 5;
    const int n  = n0 + tn;
    __half* R = g_r + (size_t)b * MR * NTOK;

    __shared__ float red[8][33];
    __shared__ float red2[8][33];
    __shared__ float zs[32];

    float m = -1e30f;
    for (int c = tc; c < MR; c += 8)
        m = fmaxf(m, __half2float(R[(size_t)c * NTOK + n]));
    red[tc][tn] = m;
    __syncthreads();
    if (tc == 0) {
        float mm = red[0][tn];
        #pragma unroll
        for (int i = 1; i < 8; i++) mm = fmaxf(mm, red[i][tn]);
        red[0][tn] = mm;
    }
    __syncthreads();
    m = red[0][tn];

    float s = 0.f;
    for (int c = tc; c < MR; c += 8) {
        const size_t idx = (size_t)c * NTOK + n;
        const float e = expf(__half2float(R[idx]) - m);
        R[idx] = __float2half(e);
        s += e;
    }
    red2[tc][tn] = s;
    __syncthreads();
    if (tc == 0) {
        float ss = 0.f;
        #pragma unroll
        for (int i = 0; i < 8; i++) ss += red2[i][tn];
        const float zi = 1.0f / ss;
        g_zinv[b * NTOK + n] = zi;
        zs[tn] = zi;
    }
    __syncthreads();

    for (int row = threadIdx.x; row < MR; row += 256) {
        const __half* Rr = R + (size_t)row * NTOK + n0;
        float acc = 0.f;
        #pragma unroll 8
        for (int t = 0; t < 32; t++) acc += __half2float(Rr[t]) * zs[t];
        atomicAdd(&g_s[b * MR + row], acc);
    }
}

// =====================================================================
// K3: pooling: Xp[bh] = X[b](256x4096) @ Rn[bh]^T(4096x128), zinv folded
// grid (128 bh, 2 m-tiles)
// =====================================================================
__global__ void __launch_bounds__(256, 2) tc_pool(const float* __restrict__ x)
{
    extern __shared__ char smem[];
    const int tid = threadIdx.x;
    const int bh = blockIdx.x, b = bh >> 3, h = bh & 7;
    const int m0 = blockIdx.y * 128;
    const float* X = x + (size_t)b * CIN * NTOK + (size_t)m0 * NTOK;
    const __half* Rb = g_r + (size_t)b * MR * NTOK + (size_t)(h * 128) * NTOK;
    const float* z = g_zinv + b * NTOK;

    const int lane = tid & 31, wid = tid >> 5;
    const int wm = (wid >> 1) * 32, wn = (wid & 1) * 64;
    const int g = lane >> 2, tig = lane & 3;

    float acc[2][8][4];
    #pragma unroll
    for (int i = 0; i < 2; i++)
        #pragma unroll
        for (int j = 0; j < 8; j++)
            #pragma unroll
            for (int k = 0; k < 4; k++) acc[i][j][k] = 0.f;

    for (int k0 = 0; k0 < NTOK; k0 += 64) {
        load_A_f32(smem, X + k0, NTOK);
        load_B_h16_scaled(smem, Rb + k0, NTOK, z + k0);
        __syncthreads();
        compute_chunk(smem, acc, wm, wn, g, tig);
        __syncthreads();
    }

    float* Xp = g_xp + (size_t)bh * CIN * 128;
    #pragma unroll
    for (int mt = 0; mt < 2; mt++) {
        const int r_a = m0 + wm + mt * 16 + g;
        const int r_b = r_a + 8;
        #pragma unroll
        for (int nt = 0; nt < 8; nt++) {
            const int nn = wn + nt * 8 + tig * 2;
            float2 va; va.x = acc[mt][nt][0]; va.y = acc[mt][nt][1];
            float2 vb; vb.x = acc[mt][nt][2]; vb.y = acc[mt][nt][3];
            *(float2*)(Xp + (size_t)r_a * 128 + nn) = va;
            *(float2*)(Xp + (size_t)r_b * 128 + nn) = vb;
        }
    }
}

// =====================================================================
// K3.5: qr/kr/vr from pooled X. grid (128 bh, 2 jsub), 256 threads
// =====================================================================
__global__ void __launch_bounds__(256) qkvr_kernel(
    const float* __restrict__ Wqkv, const float* __restrict__ bqkv)
{
    const int bh = blockIdx.x;
    const int b = bh >> 3, h = bh & 7;
    const int jsub = blockIdx.y;
    const int tid = threadIdx.x;
    const int jloc = tid & 31;
    const int j = jsub * 32 + jloc;
    const int g = tid >> 5;

    __shared__ float Ws[96][33];
    __shared__ float Xs[32][129];
    const float* Xp = g_xp + (size_t)bh * CIN * 128;

    float acc[12];
    #pragma unroll
    for (int i = 0; i < 12; i++) acc[i] = 0.f;

    for (int c0 = 0; c0 < CIN; c0 += 32) {
        for (int idx = tid; idx < 96 * 32; idx += 256)
            Ws[idx >> 5][idx & 31] = Wqkv[(size_t)(h * 96 + (idx >> 5)) * CIN + c0 + (idx & 31)];
        for (int idx = tid; idx < 32 * 128; idx += 256)
            Xs[idx >> 7][idx & 127] = Xp[(size_t)(c0 + (idx >> 7)) * 128 + (idx & 127)];
        __syncthreads();
        #pragma unroll 8
        for (int cc = 0; cc < 32; cc++) {
            const float xq = Xs[cc][j];
            const float xk = Xs[cc][j + 64];
            #pragma unroll
            for (int i = 0; i < 12; i++) {
                const int row = g * 12 + i;
                acc[i] += Ws[row][cc] * (row < 32 ? xq : xk);
            }
        }
        __syncthreads();
    }

    float* out = g_pool + (size_t)bh * 3 * 2048;
    #pragma unroll
    for (int i = 0; i < 12; i++) {
        const int row = g * 12 + i;
        const int mat = row >> 5, d = row & 31;
        const int jj = (mat == 0) ? j : j + 64;
        const float Sv = g_s[b * MR + h * 128 + jj];
        out[mat * 2048 + d * 64 + j] = acc[i] + bqkv[h * 96 + row] * Sv;
    }
}

// =====================================================================
// K4: tiny region attention per (b,h)
// =====================================================================
__global__ void __launch_bounds__(256) attn_kernel()
{
    const int bh = blockIdx.x;
    const float* pool = g_pool + (size_t)bh * 3 * 2048;
    __shared__ float qr[2048], kr[2048], vr[2048];
    __shared__ float L[64][65];
    const int tid = threadIdx.x;

    for (int i = tid; i < 2048; i += 256) {
        qr[i] = pool[i]; kr[i] = pool[2048 + i]; vr[i] = pool[4096 + i];
    }
    __syncthreads();

    const float scale = rsqrtf(32.0f);
    for (int i = tid; i < 4096; i += 256) {
        const int q = i >> 6, k = i & 63;
        float s = 0.f;
        #pragma unroll
        for (int d = 0; d < 32; d++) s += qr[d * 64 + q] * kr[d * 64 + k];
        L[q][k] = s * scale;
    }
    __syncthreads();
    if (tid < 64) {
        const int q = tid;
        float m = -1e30f;
        #pragma unroll
        for (int k = 0; k < 64; k++) m = fmaxf(m, L[q][k]);
        float s = 0.f;
        #pragma unroll
        for (int k = 0; k < 64; k++) { const float e = expf(L[q][k] - m); L[q][k] = e; s += e; }
        const float inv = 1.f / s;
        #pragma unroll
        for (int k = 0; k < 64; k++) L[q][k] *= inv;
    }
    __syncthreads();
    float* out = g_vals + (size_t)bh * 2048;
    for (int i = tid; i < 2048; i += 256) {
        const int d = i >> 6, q = i & 63;
        float s = 0.f;
        #pragma unroll
        for (int k = 0; k < 64; k++) s += vr[d * 64 + k] * L[q][k];
        out[i] = s;
    }
}

// =====================================================================
// K5: fold Wout into region values
// =====================================================================
__global__ void __launch_bounds__(256) w2_kernel(const float* __restrict__ Wout)
{
    const int b = blockIdx.y;
    const int i = blockIdx.x * 256 + threadIdx.x;
    const int c = i >> 9, hq = i & 511;
    const int h = hq >> 6, q = hq & 63;
    const float* vals = g_vals + (size_t)(b * 8 + h) * 2048;
    float s = 0.f;
    #pragma unroll
    for (int d = 0; d < 32; d++)
        s += Wout[c * 256 + h * 32 + d] * vals[d * 64 + q];
    g_W2[((size_t)b * 256 + c) * 512 + hq] = s;
}

// =====================================================================
// K6: expand GEMM + residual epilogue
// C[b] = W2(256x512) @ Rsel(512x4096); out = x + alpha*(C*zinv + bout)
// =====================================================================
__global__ void __launch_bounds__(256, 2) tc_out(
    float* __restrict__ out, const float* __restrict__ x,
    const float* __restrict__ bout, const float* __restrict__ alpha)
{
    extern __shared__ char smem[];
    const int tid = threadIdx.x;
    const int b = blockIdx.z, m0 = blockIdx.y * 128, n0 = blockIdx.x * 128;
    const float* A = g_W2 + (size_t)b * 256 * 512;
    const __half* Rbase = g_r + (size_t)b * MR * NTOK;

    const int lane = tid & 31, wid = tid >> 5;
    const int wm = (wid >> 1) * 32, wn = (wid & 1) * 64;
    const int g = lane >> 2, tig = lane & 3;

    float acc[2][8][4];
    #pragma unroll
    for (int i = 0; i < 2; i++)
        #pragma unroll
        for (int j = 0; j < 8; j++)
            #pragma unroll
            for (int k = 0; k < 4; k++) acc[i][j][k] = 0.f;

    for (int k0 = 0; k0 < 512; k0 += 64) {
        load_A_f32(smem, A + (size_t)m0 * 512 + k0, 512);
        // chunk k0 covers r rows (k0>>6)*128 .. +63 (the Rq half of each head)
        load_B_trans_h16(smem, Rbase + (size_t)((k0 >> 6) * 128) * NTOK + n0, NTOK);
        __syncthreads();
        compute_chunk(smem, acc, wm, wn, g, tig);
        __syncthreads();
    }

    const float av = *alpha;
    #pragma unroll
    for (int mt = 0; mt < 2; mt++) {
        const int c_a = m0 + wm + mt * 16 + g;
        const int c_b = c_a + 8;
        const float ba = bout[c_a], bb = bout[c_b];
        const size_t base_a = ((size_t)b * 256 + c_a) * NTOK + n0 + wn;
        const size_t base_b = ((size_t)b * 256 + c_b) * NTOK + n0 + wn;
        #pragma unroll
        for (int nt = 0; nt < 8; nt++) {
            const int nn = nt * 8 + tig * 2;
            const int n = n0 + wn + nn;
            const float z0 = g_zinv[b * NTOK + n];
            const float z1 = g_zinv[b * NTOK + n + 1];
            float2 xa = *(const float2*)(x + base_a + nn);
            float2 xb = *(const float2*)(x + base_b + nn);
            float2 oa, ob;
            oa.x = xa.x + av * (acc[mt][nt][0] * z0 + ba);
            oa.y = xa.y + av * (acc[mt][nt][1] * z1 + ba);
            ob.x = xb.x + av * (acc[mt][nt][2] * z0 + bb);
            ob.y = xb.y + av * (acc[mt][nt][3] * z1 + bb);
            *(float2*)(out + base_a + nn) = oa;
            *(float2*)(out + base_b + nn) = ob;
        }
    }
}

// =====================================================================
extern "C" void kernel_launch(void* const* d_in, const int* in_sizes, int n_in,
                              void* d_out, int out_size)
{
    const float* x     = (const float*)d_in[0];
    const float* Wqkv  = (const float*)d_in[1];
    const float* bqkv  = (const float*)d_in[2];
    const float* Wr    = (const float*)d_in[3];
    const float* br    = (const float*)d_in[4];
    const float* Wout  = (const float*)d_in[5];
    const float* bout  = (const float*)d_in[6];
    const float* alpha = (const float*)d_in[7];
    float* out = (float*)d_out;

    zero_s<<<16, 1024>>>();

    dim3 g1(NTOK / 128, MR / 128, BATCH);
    tc_r_gemm<<<g1, 256, SMEM_BYTES>>>(x, Wr, br);

    dim3 g2(NTOK / 32, BATCH);
    softmax_r<<<g2, 256>>>();

    dim3 g3(BATCH * HEADS, 2);
    tc_pool<<<g3, 256, SMEM_BYTES>>>(x);

    dim3 g35(BATCH * HEADS, 2);
    qkvr_kernel<<<g35, 256>>>(Wqkv, bqkv);

    attn_kernel<<<BATCH * HEADS, 256>>>();

    w2_kernel<<<dim3(512, BATCH), 256>>>(Wout);

    dim3 g6(NTOK / 128, 256 / 128, BATCH);
    tc_out<<<g6, 256, SMEM_BYTES>>>(out, x, bout, alpha);
}